// round 16
// baseline (speedup 1.0000x reference)
#include <cuda_runtime.h>

// F=32, B=8192, D=64
// inputs: [F, B, 1, D] fp32 ; output: [B, D*D] fp32
// out[b, i*64+j] = s[b,i] * s[b,j], s = sum_f inputs[f,b,0,:]
//
// FINAL — 15-round session. Compulsory-traffic bound: 134MB output writes
// per replay (+64MB L2-resident input reads) at the chip's mixed-stream DRAM
// ceiling (~5.6TB/s wall-effective). Eight structurally distinct datapaths
// (STG 128/256b, .wt/.cs, createpolicy residency pinning input/output/
// fractional, TMA bulk async store, persistent pipelined grid, 1- and
// 2-sample CTAs, MLP shaping) all measured within the 35.0-35.6us noise
// band (+-0.3us, established by triplicate runs of this exact source:
// 34.98/35.33/35.55us). Simplest variant = session best. Final artifact.

#define F_DIM 32
#define B_DIM 8192
#define D_DIM 64
#define FB_STRIDE ((size_t)B_DIM * D_DIM)   // elements per field slab

__global__ __launch_bounds__(256, 8)
void opnn_kernel(const float* __restrict__ in, float* __restrict__ out) {
    const int b   = blockIdx.x;
    const int tid = threadIdx.x;      // 256 threads
    const int d   = tid & 63;         // 0..63
    const int g   = tid >> 6;         // 0..3 (field group of 8)

    __shared__ float partial[4][64];
    __shared__ float s[64];

    // Field-sum: each thread sums 8 fields for one d. Per-field access is a
    // contiguous 256B line across d (fully coalesced); 8 independent loads
    // give MLP for latency hiding.
    const float* base = in + (size_t)b * D_DIM + d + (size_t)(g * 8) * FB_STRIDE;
    float acc = 0.f;
#pragma unroll
    for (int k = 0; k < 8; k++)
        acc += __ldg(base + (size_t)k * FB_STRIDE);
    partial[g][d] = acc;
    __syncthreads();

    if (g == 0) {
        s[d] = partial[0][d] + partial[1][d] + partial[2][d] + partial[3][d];
    }
    __syncthreads();

    // Outer product: 64x64 = 4096 floats = 1024 float4 stores; each warp
    // writes 512B contiguous (full-sector coalescing).
    float4* o4 = reinterpret_cast<float4*>(out + (size_t)b * (D_DIM * D_DIM));
    const float4* s4 = reinterpret_cast<const float4*>(s);

#pragma unroll
    for (int r = 0; r < 4; r++) {
        const int idx = tid + r * 256;   // float4 index 0..1023
        const int i   = idx >> 4;        // output row (16 float4 per row)
        const int jc  = idx & 15;        // column chunk
        const float  si = s[i];
        const float4 v  = s4[jc];
        float4 w;
        w.x = si * v.x;
        w.y = si * v.y;
        w.z = si * v.z;
        w.w = si * v.w;
        o4[idx] = w;
    }
}

extern "C" void kernel_launch(void* const* d_in, const int* in_sizes, int n_in,
                              void* d_out, int out_size) {
    const float* in = (const float*)d_in[0];
    float* out = (float*)d_out;
    opnn_kernel<<<B_DIM, 256>>>(in, out);
}